// round 13
// baseline (speedup 1.0000x reference)
#include <cuda_runtime.h>

#define BB 128
#define SS 512
#define KK 4
#define DD 300
#define CC 20
#define NN 10000

// K1 (R8 measured-best): 32 nodes/block; thread = (dc, pair, cg) -> 320 thr
#define DSPLIT 5
#define DCH (DD / DSPLIT)          // 60
#define P1_TPB 320
#define P1_NODES 32
#define P1_GRID ((NN + P1_NODES - 1) / P1_NODES)   // 313

// K3 GEMM: grid (NCH, 16), 256 threads; warp = one b, lanes = node quads
#define NCH 20
#define CHN (NN / NCH)             // 500 nodes per chunk

__device__ float g_P[NN * CC];             // P = node_emb @ fc_w^T (800 KB)
__device__ float g_W[BB * NN];             // dense per-b node weights (5.1 MB)
__device__ float g_part[BB * NCH * CC];    // per-(b,chunk) logit partials
__device__ unsigned int g_done[BB];        // zero-init; self-resets each call

// ---------------------------------------------------------------------------
// K1: P[n,c] = sum_d E[n,d]*W[c,d]; split-D reduced in-block (R8 config).
// ---------------------------------------------------------------------------
__global__ void __launch_bounds__(P1_TPB, 2) p_kernel(
    const float* __restrict__ node_emb, const float* __restrict__ fc_w)
{
    __shared__ float sF[DSPLIT * CC * DCH];          // 24 KB [dc][c][d]
    __shared__ float sAcc[DSPLIT][P1_NODES * CC];    // 12.8 KB

    const int t = threadIdx.x;

    for (int i = t; i < DSPLIT * CC * DCH; i += P1_TPB) {
        const int dc = i / (CC * DCH);
        const int r  = i % (CC * DCH);
        sF[i] = fc_w[(r / DCH) * DD + dc * DCH + (r % DCH)];
    }
    __syncthreads();

    const int dc = t / 64;                 // 0..4
    const int w  = t % 64;
    const int pr = w >> 2;                 // 0..15 node-pair
    const int cg = w & 3;                  // 0..3  class-group (5 classes)
    const int n0 = blockIdx.x * P1_NODES + pr * 2;
    const int d0 = dc * DCH;

    if (n0 < NN) {                         // NN even -> pair never splits
        const float4* __restrict__ e0 = (const float4*)(node_emb + (size_t)n0 * DD + d0);
        const float4* __restrict__ e1 = (const float4*)(node_emb + (size_t)(n0 + 1) * DD + d0);
        const float4* __restrict__ f4 = (const float4*)(sF + dc * CC * DCH + cg * 5 * DCH);

        float a0[5] = {0.f, 0.f, 0.f, 0.f, 0.f};
        float a1[5] = {0.f, 0.f, 0.f, 0.f, 0.f};
        #pragma unroll
        for (int dq = 0; dq < DCH / 4; dq++) {       // 15 iters
            const float4 v0 = e0[dq];
            const float4 v1 = e1[dq];
            #pragma unroll
            for (int c5 = 0; c5 < 5; c5++) {
                const float4 fv = f4[c5 * (DCH / 4) + dq];
                a0[c5] += v0.x * fv.x + v0.y * fv.y + v0.z * fv.z + v0.w * fv.w;
                a1[c5] += v1.x * fv.x + v1.y * fv.y + v1.z * fv.z + v1.w * fv.w;
            }
        }
        #pragma unroll
        for (int c5 = 0; c5 < 5; c5++) {
            sAcc[dc][(pr * 2    ) * CC + cg * 5 + c5] = a0[c5];
            sAcc[dc][(pr * 2 + 1) * CC + cg * 5 + c5] = a1[c5];
        }
    }
    __syncthreads();

    const int base = blockIdx.x * P1_NODES * CC;
    for (int i = t; i < P1_NODES * CC; i += P1_TPB) {
        if (base + i < NN * CC) {
            float s = sAcc[0][i];
            #pragma unroll
            for (int d = 1; d < DSPLIT; d++) s += sAcc[d][i];
            g_P[base + i] = s;
        }
    }
}

// ---------------------------------------------------------------------------
// K2: scatter. Block b: dense node-weight vector in smem via spread-address
// atomics. Thread t owns s-position t (512 = SS). 5 independent random DRAM
// gathers per thread (edge_w x4, node_w x1) issued together -> one latency.
// ---------------------------------------------------------------------------
__global__ void __launch_bounds__(512) scatter_kernel(
    const int* __restrict__ X, const int* __restrict__ NX, const int* __restrict__ EW,
    const float* __restrict__ edge_w, const float* __restrict__ node_w)
{
    __shared__ __align__(16) float w[NN];  // 40 KB

    const int b = blockIdx.x;
    const int t = threadIdx.x;

    // Issue all loads before the zero-fill so DRAM latency overlaps it.
    const int  x   = X[b * SS + t];
    const int4 nx4 = ((const int4*)NX)[b * SS + t];
    const int4 ew4 = ((const int4*)EW)[b * SS + t];
    const float nw = __ldg(&node_w[x]);
    const float e0 = __ldg(&edge_w[ew4.x]);
    const float e1 = __ldg(&edge_w[ew4.y]);
    const float e2 = __ldg(&edge_w[ew4.z]);
    const float e3 = __ldg(&edge_w[ew4.w]);

    for (int i = t; i < NN; i += 512) w[i] = 0.f;
    __syncthreads();

    const float inw = 1.f - nw;
    atomicAdd(&w[x],     nw);
    atomicAdd(&w[nx4.x], inw * e0);
    atomicAdd(&w[nx4.y], inw * e1);
    atomicAdd(&w[nx4.z], inw * e2);
    atomicAdd(&w[nx4.w], inw * e3);
    __syncthreads();

    float4* __restrict__ dst = (float4*)(g_W + (size_t)b * NN);
    const float4* __restrict__ src = (const float4*)w;
    #pragma unroll
    for (int i = t; i < NN / 4; i += 512) dst[i] = src[i];   // 5 iters
}

// ---------------------------------------------------------------------------
// K3: logits = W @ P as dense tiled GEMM; warp = one b, lanes = node quads.
// All W loads coalesced LDG.128; P chunk in smem. Last warp per b finalizes.
// ---------------------------------------------------------------------------
__global__ void __launch_bounds__(256) gemm_kernel(
    const float* __restrict__ fc_b, float* __restrict__ out)
{
    __shared__ __align__(16) float sP[CHN * CC];     // 40 KB

    const int chunk = blockIdx.x;
    const int bg    = blockIdx.y;
    const int t     = threadIdx.x;
    const int warp  = t >> 5;
    const int lane  = t & 31;
    const int b     = bg * 8 + warp;
    const int n0    = chunk * CHN;

    // Stage P chunk (2500 float4 coalesced over 256 threads)
    {
        const float4* __restrict__ src = (const float4*)(g_P + (size_t)n0 * CC);
        float4* dst = (float4*)sP;
        for (int i = t; i < CHN * CC / 4; i += 256) dst[i] = src[i];
    }
    __syncthreads();

    float acc[CC];
    #pragma unroll
    for (int c = 0; c < CC; c++) acc[c] = 0.f;

    const float4* __restrict__ Wrow = (const float4*)(g_W + (size_t)b * NN + n0);
    #pragma unroll
    for (int j = 0; j < 4; j++) {                    // 125 float4 over 32 lanes
        const int idx4 = lane + j * 32;
        if (idx4 < CHN / 4) {
            const float4 wv = Wrow[idx4];            // coalesced across warp
            #pragma unroll
            for (int jj = 0; jj < 4; jj++) {
                const float wj = (&wv.x)[jj];
                const float4* __restrict__ p4 = (const float4*)(sP + (idx4 * 4 + jj) * CC);
                #pragma unroll
                for (int c4 = 0; c4 < 5; c4++) {
                    const float4 pv = p4[c4];
                    acc[c4 * 4 + 0] += wj * pv.x;
                    acc[c4 * 4 + 1] += wj * pv.y;
                    acc[c4 * 4 + 2] += wj * pv.z;
                    acc[c4 * 4 + 3] += wj * pv.w;
                }
            }
        }
    }

    // Butterfly reduce over lanes (all lanes end with full sums; fixed order)
    #pragma unroll
    for (int o = 16; o; o >>= 1)
        #pragma unroll
        for (int c = 0; c < CC; c++)
            acc[c] += __shfl_xor_sync(0xffffffffu, acc[c], o);

    if (lane < CC) g_part[(b * NCH + chunk) * CC + lane] = acc[lane];

    // Last-arriving chunk warp for this b does bias+relu+softmax
    unsigned last = 0;
    if (lane == 0) {
        __threadfence();                              // release my partial
        last = (atomicAdd(&g_done[b], 1u) == NCH - 1) ? 1u : 0u;
    }
    last = __shfl_sync(0xffffffffu, last, 0);
    if (last) {
        if (lane == 0) {
            g_done[b] = 0;                            // reset for graph replay
            __threadfence();                          // acquire partials
        }
        __syncwarp();
        float l = -1e30f;
        if (lane < CC) {
            float s = fc_b[lane];
            #pragma unroll
            for (int ch = 0; ch < NCH; ch++)
                s += g_part[(b * NCH + ch) * CC + lane];
            l = fmaxf(s, 0.f);
        }
        float mx = l;
        #pragma unroll
        for (int o = 16; o; o >>= 1) mx = fmaxf(mx, __shfl_xor_sync(0xffffffffu, mx, o));
        const float e = (lane < CC) ? __expf(l - mx) : 0.f;
        float sum = e;
        #pragma unroll
        for (int o = 16; o; o >>= 1) sum += __shfl_xor_sync(0xffffffffu, sum, o);
        if (lane < CC) out[b * CC + lane] = e / sum;
    }
}

// ---------------------------------------------------------------------------
extern "C" void kernel_launch(void* const* d_in, const int* in_sizes, int n_in,
                              void* d_out, int out_size)
{
    const int*   X        = (const int*)  d_in[0];
    const int*   NX       = (const int*)  d_in[1];
    const int*   EW       = (const int*)  d_in[2];
    const float* node_emb = (const float*)d_in[3];
    const float* edge_w   = (const float*)d_in[4];
    const float* node_w   = (const float*)d_in[5];
    const float* fc_w     = (const float*)d_in[6];
    const float* fc_b     = (const float*)d_in[7];
    float* out = (float*)d_out;

    p_kernel<<<P1_GRID, P1_TPB>>>(node_emb, fc_w);
    scatter_kernel<<<BB, 512>>>(X, NX, EW, edge_w, node_w);
    dim3 grid3(NCH, BB / 8);
    gemm_kernel<<<grid3, 256>>>(fc_b, out);
}

// round 14
// speedup vs baseline: 1.3509x; 1.3509x over previous
#include <cuda_runtime.h>

#define BB 128
#define SS 512
#define KK 4
#define DD 300
#define CC 20
#define NN 10000
#define PROW 32                    // padded P row (128B, line-aligned)

// K1: 32 nodes/block; thread = (dc 0..4, pair 0..15, cg 0..3) -> 320 threads
#define DSPLIT 5
#define DCH (DD / DSPLIT)          // 60
#define P1_TPB 320
#define P1_NODES 32
#define P1_GRID ((NN + P1_NODES - 1) / P1_NODES)   // 313
#define PF_BLKS 87                 // prefetch-only blocks appended to K1 grid
#define K1_GRID (P1_GRID + PF_BLKS)

// K2: grid (GCH, BB), 320 threads; thread = (s-group 0..63, quad 0..4)
#define GCH 4
#define SCH (SS / GCH)             // 128
#define G_TPB 320
#define G_GRP 64

#define EWN (BB * SS * KK)         // 262144

__device__ __align__(128) float g_P[NN * PROW];   // padded P (1.28 MB, L2-resident)
__device__ float g_EW[EWN];                       // prefetched edge weights (1 MB)
__device__ float g_part[BB * GCH * CC];           // per-(b,chunk) logit partials
__device__ unsigned int g_done[BB];               // zero-init; self-resets each call

// ---------------------------------------------------------------------------
// K1: blocks [0,313) = P-GEMM (R8 measured-best config);
//     blocks [313,400) = random edge_w prefetch on otherwise-idle DRAM.
// ---------------------------------------------------------------------------
__global__ void __launch_bounds__(P1_TPB, 2) p_kernel(
    const float* __restrict__ node_emb, const float* __restrict__ fc_w,
    const int* __restrict__ EW, const float* __restrict__ edge_w)
{
    const int t = threadIdx.x;

    if (blockIdx.x >= P1_GRID) {
        // Prefetch role: ~9.4 independent EW->edge_w chains per thread.
        const int pb = blockIdx.x - P1_GRID;
        for (int i = pb * P1_TPB + t; i < EWN; i += PF_BLKS * P1_TPB)
            g_EW[i] = __ldg(&edge_w[__ldg(&EW[i])]);
        return;
    }

    __shared__ float sF[DSPLIT * CC * DCH];          // 24 KB [dc][c][d]
    __shared__ float sAcc[DSPLIT][P1_NODES * CC];    // 12.8 KB

    for (int i = t; i < DSPLIT * CC * DCH; i += P1_TPB) {
        const int dc = i / (CC * DCH);
        const int r  = i % (CC * DCH);
        sF[i] = fc_w[(r / DCH) * DD + dc * DCH + (r % DCH)];
    }
    __syncthreads();

    const int dc = t / 64;                 // 0..4
    const int w  = t % 64;
    const int pr = w >> 2;                 // 0..15 node-pair
    const int cg = w & 3;                  // 0..3  class-group (5 classes)
    const int n0 = blockIdx.x * P1_NODES + pr * 2;
    const int d0 = dc * DCH;

    if (n0 < NN) {                         // NN even -> pair never splits
        const float4* __restrict__ e0 = (const float4*)(node_emb + (size_t)n0 * DD + d0);
        const float4* __restrict__ e1 = (const float4*)(node_emb + (size_t)(n0 + 1) * DD + d0);
        const float4* __restrict__ f4 = (const float4*)(sF + dc * CC * DCH + cg * 5 * DCH);

        float a0[5] = {0.f, 0.f, 0.f, 0.f, 0.f};
        float a1[5] = {0.f, 0.f, 0.f, 0.f, 0.f};
        #pragma unroll
        for (int dq = 0; dq < DCH / 4; dq++) {       // 15 iters
            const float4 v0 = e0[dq];
            const float4 v1 = e1[dq];
            #pragma unroll
            for (int c5 = 0; c5 < 5; c5++) {
                const float4 fv = f4[c5 * (DCH / 4) + dq];
                a0[c5] += v0.x * fv.x + v0.y * fv.y + v0.z * fv.z + v0.w * fv.w;
                a1[c5] += v1.x * fv.x + v1.y * fv.y + v1.z * fv.z + v1.w * fv.w;
            }
        }
        #pragma unroll
        for (int c5 = 0; c5 < 5; c5++) {
            sAcc[dc][(pr * 2    ) * CC + cg * 5 + c5] = a0[c5];
            sAcc[dc][(pr * 2 + 1) * CC + cg * 5 + c5] = a1[c5];
        }
    }
    __syncthreads();

    // Reduce 5 d-chunk partials -> padded g_P rows (row n at 128B boundary)
    const int nb = blockIdx.x * P1_NODES;
    for (int i = t; i < P1_NODES * CC; i += P1_TPB) {
        const int nl = i / CC, c = i % CC;
        if (nb + nl < NN) {
            float s = sAcc[0][i];
            #pragma unroll
            for (int d = 1; d < DSPLIT; d++) s += sAcc[d][i];
            g_P[(size_t)(nb + nl) * PROW + c] = s;
        }
    }
}

// ---------------------------------------------------------------------------
// K2: gather on line-aligned padded P. Thread = (s-group, class-quad); the
// 5 quads of one row hit ONE 128B line -> ~7 wavefronts/warp-instr (was ~26).
// Last-arriving chunk block per b combines partials + softmax.
// ---------------------------------------------------------------------------
__global__ void __launch_bounds__(G_TPB) gather_kernel(
    const int* __restrict__ X, const int* __restrict__ NX,
    const float* __restrict__ node_w,
    const float* __restrict__ fc_b, float* __restrict__ out)
{
    __shared__ int   sX[SCH];
    __shared__ float sNW[SCH];
    __shared__ int   sNX[SCH * KK];
    __shared__ float sEW[SCH * KK];
    __shared__ float sred[G_GRP][CC];      // 5 KB

    const int ch = blockIdx.x;
    const int b  = blockIdx.y;
    const int s0 = ch * SCH;
    const int t  = threadIdx.x;

    // Coalesced staging (edge weights pre-resolved in g_EW by K1's PF blocks)
    for (int i = t; i < SCH * KK; i += G_TPB) sEW[i] = g_EW[(b * SS + s0) * KK + i];
    for (int i = t; i < SCH * KK; i += G_TPB) sNX[i] = NX[(b * SS + s0) * KK + i];
    for (int i = t; i < SCH; i += G_TPB)      sX[i]  = X[b * SS + s0 + i];
    __syncthreads();
    for (int i = t; i < SCH; i += G_TPB)      sNW[i] = __ldg(&node_w[sX[i]]);
    __syncthreads();

    const int g = t / 5;                   // 0..63 s-group
    const int q = t % 5;                   // 0..4  class quad
    const float4* __restrict__ P4 = (const float4*)g_P;   // padded stride 8

    float4 acc = make_float4(0.f, 0.f, 0.f, 0.f);
    #pragma unroll
    for (int i = 0; i < SCH / G_GRP; i++) {        // 2 s-positions per thread
        const int s = g + i * G_GRP;
        const float nw = sNW[s];
        float4 m = make_float4(0.f, 0.f, 0.f, 0.f);
        #pragma unroll
        for (int k = 0; k < KK; k++) {
            const float  ew = sEW[s * KK + k];
            const float4 p  = __ldg(&P4[(size_t)sNX[s * KK + k] * 8 + q]);
            m.x += ew * p.x; m.y += ew * p.y; m.z += ew * p.z; m.w += ew * p.w;
        }
        const float4 r = __ldg(&P4[(size_t)sX[s] * 8 + q]);
        const float inw = 1.f - nw;
        acc.x += inw * m.x + nw * r.x;
        acc.y += inw * m.y + nw * r.y;
        acc.z += inw * m.z + nw * r.z;
        acc.w += inw * m.w + nw * r.w;
    }
    *(float4*)&sred[g][q * 4] = acc;
    __syncthreads();

    // Fixed-order tree reduce over 64 s-groups -> deterministic
    #pragma unroll
    for (int off = G_GRP / 2; off > 0; off >>= 1) {
        if (t < off * 5) {
            const int gg = t / 5, qq = t % 5;
            float4 a = *(float4*)&sred[gg][qq * 4];
            float4 bb = *(float4*)&sred[gg + off][qq * 4];
            a.x += bb.x; a.y += bb.y; a.z += bb.z; a.w += bb.w;
            *(float4*)&sred[gg][qq * 4] = a;
        }
        __syncthreads();
    }

    if (t < CC) g_part[(b * GCH + ch) * CC + t] = sred[0][t];
    __syncthreads();

    if (t < 32) {
        unsigned last = 0;
        if (t == 0) {
            __threadfence();                               // release my partial
            last = (atomicAdd(&g_done[b], 1u) == GCH - 1) ? 1u : 0u;
        }
        last = __shfl_sync(0xffffffffu, last, 0);
        if (last) {
            if (t == 0) {
                g_done[b] = 0;                             // reset for replay
                __threadfence();                           // acquire partials
            }
            __syncwarp();
            float l = -1e30f;
            if (t < CC) {
                float s = fc_b[t];
                #pragma unroll
                for (int qch = 0; qch < GCH; qch++)
                    s += g_part[(b * GCH + qch) * CC + t];
                l = fmaxf(s, 0.f);
            }
            float mx = l;
            #pragma unroll
            for (int o = 16; o; o >>= 1) mx = fmaxf(mx, __shfl_xor_sync(0xffffffffu, mx, o));
            const float e = (t < CC) ? __expf(l - mx) : 0.f;
            float sum = e;
            #pragma unroll
            for (int o = 16; o; o >>= 1) sum += __shfl_xor_sync(0xffffffffu, sum, o);
            if (t < CC) out[b * CC + t] = e / sum;
        }
    }
}

// ---------------------------------------------------------------------------
extern "C" void kernel_launch(void* const* d_in, const int* in_sizes, int n_in,
                              void* d_out, int out_size)
{
    const int*   X        = (const int*)  d_in[0];
    const int*   NX       = (const int*)  d_in[1];
    const int*   EW       = (const int*)  d_in[2];
    const float* node_emb = (const float*)d_in[3];
    const float* edge_w   = (const float*)d_in[4];
    const float* node_w   = (const float*)d_in[5];
    const float* fc_w     = (const float*)d_in[6];
    const float* fc_b     = (const float*)d_in[7];
    float* out = (float*)d_out;

    p_kernel<<<K1_GRID, P1_TPB>>>(node_emb, fc_w, EW, edge_w);
    dim3 grid2(GCH, BB);
    gather_kernel<<<grid2, G_TPB>>>(X, NX, node_w, fc_b, out);
}

// round 15
// speedup vs baseline: 1.6213x; 1.2002x over previous
#include <cuda_runtime.h>

#define BB 128
#define SS 512
#define KK 4
#define DD 300
#define CC 20
#define NN 10000
#define PROW 32                    // padded P row: 128B, line-aligned

// K1: 32 nodes/block; thread = (dc 0..2, pair 0..15, cg 0..3) -> 192 threads
#define DSPLIT 3
#define DCH (DD / DSPLIT)          // 100
#define P1_TPB 192
#define P1_NODES 32
#define P1_GRID ((NN + P1_NODES - 1) / P1_NODES)   // 313
#define P1_THREADS (P1_GRID * P1_TPB)              // 60096

// K2: grid (GCH, BB), 320 threads; thread = (s-group 0..63, quad 0..4)
#define GCH 4
#define SCH (SS / GCH)             // 128
#define G_TPB 320
#define G_GRP 64

#define EWN (BB * SS * KK)         // 262144

__device__ __align__(128) float g_P[NN * PROW];   // padded P (1.28 MB, L2-resident)
__device__ float g_EW[EWN];              // prefetched edge weights (1 MB)
__device__ float g_part[BB * GCH * CC];  // per-(b,chunk) logit partials
__device__ unsigned int g_done[BB];      // zero-init; self-resets each call

// ---------------------------------------------------------------------------
// K1: P-GEMM (pairs x 5 classes x 3 d-chunks) + overlapped random edge_w
// prefetch (R11 measured-best config). Writes line-aligned padded P rows.
// ---------------------------------------------------------------------------
__global__ void __launch_bounds__(P1_TPB, 4) p_kernel(
    const float* __restrict__ node_emb, const float* __restrict__ fc_w,
    const int* __restrict__ EW, const float* __restrict__ edge_w)
{
    __shared__ float sF[DSPLIT * CC * DCH];          // 24 KB, [dc][c][d]
    __shared__ float sAcc[DSPLIT][P1_NODES * CC];    // 7.7 KB

    const int t = threadIdx.x;

    // Stage fc_w rearranged [dc][c][d-within-chunk]
    for (int i = t; i < DSPLIT * CC * DCH; i += P1_TPB) {
        const int dc = i / (CC * DCH);
        const int r  = i % (CC * DCH);
        sF[i] = fc_w[(r / DCH) * DD + dc * DCH + (r % DCH)];
    }

    // Overlapped random edge_w prefetch (~4.4 independent chains/thread);
    // coalesced writes to g_EW, consumed by K2 via stream order.
    for (int i = blockIdx.x * P1_TPB + t; i < EWN; i += P1_THREADS)
        g_EW[i] = __ldg(&edge_w[__ldg(&EW[i])]);

    __syncthreads();

    const int dc = t / 64;                 // 0..2
    const int w  = t % 64;
    const int pr = w >> 2;                 // 0..15 node-pair
    const int cg = w & 3;                  // 0..3  class-group (5 classes)
    const int n0 = blockIdx.x * P1_NODES + pr * 2;
    const int d0 = dc * DCH;

    if (n0 < NN) {                         // NN even -> pair never splits
        const float4* __restrict__ e0 = (const float4*)(node_emb + (size_t)n0 * DD + d0);
        const float4* __restrict__ e1 = (const float4*)(node_emb + (size_t)(n0 + 1) * DD + d0);
        const float4* __restrict__ f4 = (const float4*)(sF + dc * CC * DCH + cg * 5 * DCH);

        float a0[5] = {0.f, 0.f, 0.f, 0.f, 0.f};
        float a1[5] = {0.f, 0.f, 0.f, 0.f, 0.f};
        #pragma unroll 5
        for (int dq = 0; dq < DCH / 4; dq++) {       // 25 iters
            const float4 v0 = e0[dq];
            const float4 v1 = e1[dq];
            #pragma unroll
            for (int c5 = 0; c5 < 5; c5++) {
                const float4 fv = f4[c5 * (DCH / 4) + dq];
                a0[c5] += v0.x * fv.x + v0.y * fv.y + v0.z * fv.z + v0.w * fv.w;
                a1[c5] += v1.x * fv.x + v1.y * fv.y + v1.z * fv.z + v1.w * fv.w;
            }
        }
        #pragma unroll
        for (int c5 = 0; c5 < 5; c5++) {
            sAcc[dc][(pr * 2    ) * CC + cg * 5 + c5] = a0[c5];
            sAcc[dc][(pr * 2 + 1) * CC + cg * 5 + c5] = a1[c5];
        }
    }
    __syncthreads();

    // Reduce 3 d-chunk partials -> padded g_P rows (each row on a 128B line)
    const int nb = blockIdx.x * P1_NODES;
    for (int i = t; i < P1_NODES * CC; i += P1_TPB) {
        const int nl = i / CC, c = i % CC;
        if (nb + nl < NN)
            g_P[(size_t)(nb + nl) * PROW + c] = sAcc[0][i] + sAcc[1][i] + sAcc[2][i];
    }
}

// ---------------------------------------------------------------------------
// K2: vectorized gather on line-aligned P (R11 config + padding). Thread =
// (s-group g, quad q): the 5 quads of a row share ONE 128B line.
// Last-arriving chunk block per b combines partials + softmax.
// ---------------------------------------------------------------------------
__global__ void __launch_bounds__(G_TPB) gather_kernel(
    const int* __restrict__ X, const int* __restrict__ NX,
    const float* __restrict__ node_w,
    const float* __restrict__ fc_b, float* __restrict__ out)
{
    __shared__ int   sX[SCH];
    __shared__ float sNW[SCH];
    __shared__ int   sNX[SCH * KK];
    __shared__ float sEW[SCH * KK];
    __shared__ float sred[G_GRP][CC];      // 5 KB

    const int ch = blockIdx.x;
    const int b  = blockIdx.y;
    const int s0 = ch * SCH;
    const int t  = threadIdx.x;

    // Coalesced staging (edge weights pre-resolved in g_EW by K1)
    for (int i = t; i < SCH * KK; i += G_TPB) sEW[i] = g_EW[(b * SS + s0) * KK + i];
    for (int i = t; i < SCH * KK; i += G_TPB) sNX[i] = NX[(b * SS + s0) * KK + i];
    for (int i = t; i < SCH; i += G_TPB)      sX[i]  = X[b * SS + s0 + i];
    __syncthreads();
    for (int i = t; i < SCH; i += G_TPB)      sNW[i] = __ldg(&node_w[sX[i]]);
    __syncthreads();

    const int g = t / 5;                   // 0..63 s-group
    const int q = t % 5;                   // 0..4  class quad
    const float4* __restrict__ P4 = (const float4*)g_P;   // padded row stride 8

    float4 acc = make_float4(0.f, 0.f, 0.f, 0.f);
    #pragma unroll
    for (int i = 0; i < SCH / G_GRP; i++) {        // 2 s-positions per thread
        const int s = g + i * G_GRP;
        const float nw = sNW[s];
        float4 m = make_float4(0.f, 0.f, 0.f, 0.f);
        #pragma unroll
        for (int k = 0; k < KK; k++) {
            const float  ew = sEW[s * KK + k];
            const float4 p  = __ldg(&P4[(size_t)sNX[s * KK + k] * 8 + q]);
            m.x += ew * p.x; m.y += ew * p.y; m.z += ew * p.z; m.w += ew * p.w;
        }
        const float4 r = __ldg(&P4[(size_t)sX[s] * 8 + q]);
        const float inw = 1.f - nw;
        acc.x += inw * m.x + nw * r.x;
        acc.y += inw * m.y + nw * r.y;
        acc.z += inw * m.z + nw * r.z;
        acc.w += inw * m.w + nw * r.w;
    }
    *(float4*)&sred[g][q * 4] = acc;
    __syncthreads();

    // Fixed-order tree reduce over 64 s-groups -> deterministic
    #pragma unroll
    for (int off = G_GRP / 2; off > 0; off >>= 1) {
        if (t < off * 5) {
            const int gg = t / 5, qq = t % 5;
            float4 a = *(float4*)&sred[gg][qq * 4];
            float4 bb = *(float4*)&sred[gg + off][qq * 4];
            a.x += bb.x; a.y += bb.y; a.z += bb.z; a.w += bb.w;
            *(float4*)&sred[gg][qq * 4] = a;
        }
        __syncthreads();
    }

    if (t < CC) g_part[(b * GCH + ch) * CC + t] = sred[0][t];
    __syncthreads();

    if (t < 32) {
        unsigned last = 0;
        if (t == 0) {
            __threadfence();                               // release my partial
            last = (atomicAdd(&g_done[b], 1u) == GCH - 1) ? 1u : 0u;
        }
        last = __shfl_sync(0xffffffffu, last, 0);
        if (last) {
            if (t == 0) {
                g_done[b] = 0;                             // reset for replay
                __threadfence();                           // acquire partials
            }
            __syncwarp();
            float l = -1e30f;
            if (t < CC) {
                float s = fc_b[t];
                #pragma unroll
                for (int qch = 0; qch < GCH; qch++)
                    s += g_part[(b * GCH + qch) * CC + t];
                l = fmaxf(s, 0.f);
            }
            float mx = l;
            #pragma unroll
            for (int o = 16; o; o >>= 1) mx = fmaxf(mx, __shfl_xor_sync(0xffffffffu, mx, o));
            const float e = (t < CC) ? __expf(l - mx) : 0.f;
            float sum = e;
            #pragma unroll
            for (int o = 16; o; o >>= 1) sum += __shfl_xor_sync(0xffffffffu, sum, o);
            if (t < CC) out[b * CC + t] = e / sum;
        }
    }
}

// ---------------------------------------------------------------------------
extern "C" void kernel_launch(void* const* d_in, const int* in_sizes, int n_in,
                              void* d_out, int out_size)
{
    const int*   X        = (const int*)  d_in[0];
    const int*   NX       = (const int*)  d_in[1];
    const int*   EW       = (const int*)  d_in[2];
    const float* node_emb = (const float*)d_in[3];
    const float* edge_w   = (const float*)d_in[4];
    const float* node_w   = (const float*)d_in[5];
    const float* fc_w     = (const float*)d_in[6];
    const float* fc_b     = (const float*)d_in[7];
    float* out = (float*)d_out;

    p_kernel<<<P1_GRID, P1_TPB>>>(node_emb, fc_w, EW, edge_w);
    dim3 grid2(GCH, BB);
    gather_kernel<<<grid2, G_TPB>>>(X, NX, node_w, fc_b, out);
}

// round 16
// speedup vs baseline: 1.6592x; 1.0234x over previous
#include <cuda_runtime.h>

#define BB 128
#define SS 512
#define KK 4
#define DD 300
#define CC 20
#define NN 10000
#define PROW 32                    // padded P row: 128B, line-aligned

// K1: 16 nodes/block; thread = (dc 0..4, pair 0..7, cg 0..3) -> 160 threads
#define DSPLIT 5
#define DCH (DD / DSPLIT)          // 60
#define P1_TPB 160
#define P1_NODES 16
#define P1_GRID ((NN + P1_NODES - 1) / P1_NODES)   // 625
#define P1_THREADS (P1_GRID * P1_TPB)              // 100000

// K2: grid (GCH, BB), 320 threads; thread = (s-group 0..63, quad 0..4)
#define GCH 4
#define SCH (SS / GCH)             // 128
#define G_TPB 320
#define G_GRP 64

#define EWN (BB * SS * KK)         // 262144

__device__ __align__(128) float g_P[NN * PROW];   // padded P (1.28 MB, L2-resident)
__device__ float g_EW[EWN];              // prefetched edge weights (1 MB)
__device__ float g_part[BB * GCH * CC];  // per-(b,chunk) logit partials
__device__ unsigned int g_done[BB];      // zero-init; self-resets each call

// Packed dual-FMA: acc(f32x2) += a(f32x2) * b(f32x2). ptxas never emits this
// from C++; on sm_103a it halves FMA issue slots.
#define FMA2(acc, a, b) \
    asm("fma.rn.f32x2 %0, %1, %2, %0;" : "+l"(acc) : "l"(a), "l"(b))

__device__ __forceinline__ float f32x2_sum(unsigned long long v) {
    float lo = __uint_as_float((unsigned)(v & 0xffffffffull));
    float hi = __uint_as_float((unsigned)(v >> 32));
    return lo + hi;
}

// ---------------------------------------------------------------------------
// K1: P-GEMM with f32x2 packed FMA (even/odd d lanes) + overlapped random
// edge_w prefetch. 625 blocks x 160 thr (~21 warps/SM).
// ---------------------------------------------------------------------------
__global__ void __launch_bounds__(P1_TPB, 7) p_kernel(
    const float* __restrict__ node_emb, const float* __restrict__ fc_w,
    const int* __restrict__ EW, const float* __restrict__ edge_w)
{
    __shared__ __align__(16) float sF[DSPLIT * CC * DCH];   // 24 KB [dc][c][d]
    __shared__ float sAcc[DSPLIT][P1_NODES * CC];           // 6.4 KB

    const int t = threadIdx.x;

    // Stage fc_w rearranged [dc][c][d-within-chunk]
    for (int i = t; i < DSPLIT * CC * DCH; i += P1_TPB) {
        const int dc = i / (CC * DCH);
        const int r  = i % (CC * DCH);
        sF[i] = fc_w[(r / DCH) * DD + dc * DCH + (r % DCH)];
    }

    // Overlapped random edge_w prefetch (~2.6 independent chains/thread);
    // coalesced writes to g_EW, consumed by K2 via stream order.
    for (int i = blockIdx.x * P1_TPB + t; i < EWN; i += P1_THREADS)
        g_EW[i] = __ldg(&edge_w[__ldg(&EW[i])]);

    __syncthreads();

    const int dc = t >> 5;                 // 0..4
    const int w  = t & 31;
    const int pr = w >> 2;                 // 0..7 node-pair
    const int cg = w & 3;                  // 0..3 class-group (5 classes)
    const int n0 = blockIdx.x * P1_NODES + pr * 2;
    const int d0 = dc * DCH;

    if (n0 < NN) {                         // NN even -> pair never splits
        // 16B loads viewed as packed f32x2 pairs (even/odd d)
        const ulonglong2* __restrict__ e0 =
            (const ulonglong2*)(node_emb + (size_t)n0 * DD + d0);
        const ulonglong2* __restrict__ e1 =
            (const ulonglong2*)(node_emb + (size_t)(n0 + 1) * DD + d0);
        const ulonglong2* __restrict__ f4 =
            (const ulonglong2*)(sF + dc * CC * DCH + cg * 5 * DCH);

        unsigned long long a0[5] = {0, 0, 0, 0, 0};
        unsigned long long a1[5] = {0, 0, 0, 0, 0};
        #pragma unroll
        for (int dq = 0; dq < DCH / 4; dq++) {       // 15 iters, 4 d's each
            const ulonglong2 v0 = e0[dq];
            const ulonglong2 v1 = e1[dq];
            #pragma unroll
            for (int c5 = 0; c5 < 5; c5++) {
                const ulonglong2 fv = f4[c5 * (DCH / 4) + dq];
                FMA2(a0[c5], v0.x, fv.x);
                FMA2(a0[c5], v0.y, fv.y);
                FMA2(a1[c5], v1.x, fv.x);
                FMA2(a1[c5], v1.y, fv.y);
            }
        }
        #pragma unroll
        for (int c5 = 0; c5 < 5; c5++) {
            sAcc[dc][(pr * 2    ) * CC + cg * 5 + c5] = f32x2_sum(a0[c5]);
            sAcc[dc][(pr * 2 + 1) * CC + cg * 5 + c5] = f32x2_sum(a1[c5]);
        }
    }
    __syncthreads();

    // Reduce 5 d-chunk partials -> padded g_P rows (each row on a 128B line)
    const int nb = blockIdx.x * P1_NODES;
    for (int i = t; i < P1_NODES * CC; i += P1_TPB) {
        const int nl = i / CC, c = i % CC;
        if (nb + nl < NN) {
            float s = sAcc[0][i];
            #pragma unroll
            for (int d = 1; d < DSPLIT; d++) s += sAcc[d][i];
            g_P[(size_t)(nb + nl) * PROW + c] = s;
        }
    }
}

// ---------------------------------------------------------------------------
// K2 (R15 verbatim): vectorized gather on line-aligned P.
// Last-arriving chunk block per b combines partials + softmax.
// ---------------------------------------------------------------------------
__global__ void __launch_bounds__(G_TPB) gather_kernel(
    const int* __restrict__ X, const int* __restrict__ NX,
    const float* __restrict__ node_w,
    const float* __restrict__ fc_b, float* __restrict__ out)
{
    __shared__ int   sX[SCH];
    __shared__ float sNW[SCH];
    __shared__ int   sNX[SCH * KK];
    __shared__ float sEW[SCH * KK];
    __shared__ float sred[G_GRP][CC];      // 5 KB

    const int ch = blockIdx.x;
    const int b  = blockIdx.y;
    const int s0 = ch * SCH;
    const int t  = threadIdx.x;

    for (int i = t; i < SCH * KK; i += G_TPB) sEW[i] = g_EW[(b * SS + s0) * KK + i];
    for (int i = t; i < SCH * KK; i += G_TPB) sNX[i] = NX[(b * SS + s0) * KK + i];
    for (int i = t; i < SCH; i += G_TPB)      sX[i]  = X[b * SS + s0 + i];
    __syncthreads();
    for (int i = t; i < SCH; i += G_TPB)      sNW[i] = __ldg(&node_w[sX[i]]);
    __syncthreads();

    const int g = t / 5;                   // 0..63 s-group
    const int q = t % 5;                   // 0..4  class quad
    const float4* __restrict__ P4 = (const float4*)g_P;   // padded row stride 8

    float4 acc = make_float4(0.f, 0.f, 0.f, 0.f);
    #pragma unroll
    for (int i = 0; i < SCH / G_GRP; i++) {        // 2 s-positions per thread
        const int s = g + i * G_GRP;
        const float nw = sNW[s];
        float4 m = make_float4(0.f, 0.f, 0.f, 0.f);
        #pragma unroll
        for (int k = 0; k < KK; k++) {
            const float  ew = sEW[s * KK + k];
            const float4 p  = __ldg(&P4[(size_t)sNX[s * KK + k] * 8 + q]);
            m.x += ew * p.x; m.y += ew * p.y; m.z += ew * p.z; m.w += ew * p.w;
        }
        const float4 r = __ldg(&P4[(size_t)sX[s] * 8 + q]);
        const float inw = 1.f - nw;
        acc.x += inw * m.x + nw * r.x;
        acc.y += inw * m.y + nw * r.y;
        acc.z += inw * m.z + nw * r.z;
        acc.w += inw * m.w + nw * r.w;
    }
    *(float4*)&sred[g][q * 4] = acc;
    __syncthreads();

    #pragma unroll
    for (int off = G_GRP / 2; off > 0; off >>= 1) {
        if (t < off * 5) {
            const int gg = t / 5, qq = t % 5;
            float4 a = *(float4*)&sred[gg][qq * 4];
            float4 bb = *(float4*)&sred[gg + off][qq * 4];
            a.x += bb.x; a.y += bb.y; a.z += bb.z; a.w += bb.w;
            *(float4*)&sred[gg][qq * 4] = a;
        }
        __syncthreads();
    }

    if (t < CC) g_part[(b * GCH + ch) * CC + t] = sred[0][t];
    __syncthreads();

    if (t < 32) {
        unsigned last = 0;
        if (t == 0) {
            __threadfence();                               // release my partial
            last = (atomicAdd(&g_done[b], 1u) == GCH - 1) ? 1u : 0u;
        }
        last = __shfl_sync(0xffffffffu, last, 0);
        if (last) {
            if (t == 0) {
                g_done[b] = 0;                             // reset for replay
                __threadfence();                           // acquire partials
            }
            __syncwarp();
            float l = -1e30f;
            if (t < CC) {
                float s = fc_b[t];
                #pragma unroll
                for (int qch = 0; qch < GCH; qch++)
                    s += g_part[(b * GCH + qch) * CC + t];
                l = fmaxf(s, 0.f);
            }
            float mx = l;
            #pragma unroll
            for (int o = 16; o; o >>= 1) mx = fmaxf(mx, __shfl_xor_sync(0xffffffffu, mx, o));
            const float e = (t < CC) ? __expf(l - mx) : 0.f;
            float sum = e;
            #pragma unroll
            for (int o = 16; o; o >>= 1) sum += __shfl_xor_sync(0xffffffffu, sum, o);
            if (t < CC) out[b * CC + t] = e / sum;
        }
    }
}

// ---------------------------------------------------------------------------
extern "C" void kernel_launch(void* const* d_in, const int* in_sizes, int n_in,
                              void* d_out, int out_size)
{
    const int*   X        = (const int*)  d_in[0];
    const int*   NX       = (const int*)  d_in[1];
    const int*   EW       = (const int*)  d_in[2];
    const float* node_emb = (const float*)d_in[3];
    const float* edge_w   = (const float*)d_in[4];
    const float* node_w   = (const float*)d_in[5];
    const float* fc_w     = (const float*)d_in[6];
    const float* fc_b     = (const float*)d_in[7];
    float* out = (float*)d_out;

    p_kernel<<<P1_GRID, P1_TPB>>>(node_emb, fc_w, EW, edge_w);
    dim3 grid2(GCH, BB);
    gather_kernel<<<grid2, G_TPB>>>(X, NX, node_w, fc_b, out);
}